// round 2
// baseline (speedup 1.0000x reference)
#include <cuda_runtime.h>
#include <cstdint>
#include <cstddef>

#define N_    8192
#define IND   256
#define OUTD  64
#define NS    32        // j splits
#define TM    128       // rows per attention block
#define TJ    64        // j chunk
#define WST   65        // w_s row stride (floats)
#define HST   68        // h_s row stride (floats, 16B-aligned rows)

// ---------------- device scratch (no runtime allocation allowed) ----------------
__device__ __align__(16) float g_h [N_ * OUTD];
__device__ __align__(16) float g_f1[N_];
__device__ __align__(16) float g_f2[N_];
__device__ __align__(16) float g_V [N_ * OUTD];
__device__ __align__(16) float g_S [N_];

typedef unsigned long long ull;

// ---------------- packed f32x2 helpers (sm_100+) ----------------
__device__ __forceinline__ ull pk2(float x) {
    ull u;
    asm("mov.b64 %0, {%1, %1};" : "=l"(u) : "r"(__float_as_uint(x)));
    return u;
}
__device__ __forceinline__ void ffma2(ull& d, ull a, ull b) {
    asm("fma.rn.f32x2 %0, %1, %2, %0;" : "+l"(d) : "l"(a), "l"(b));
}
__device__ __forceinline__ float2 upk(ull u) {
    float2 f;
    asm("mov.b64 {%0, %1}, %2;" : "=f"(f.x), "=f"(f.y) : "l"(u));
    return f;
}
__device__ __forceinline__ void red4(float* p, float a, float b, float c, float d) {
    asm volatile("red.global.add.v4.f32 [%0], {%1, %2, %3, %4};"
                 :: "l"(p), "f"(a), "f"(b), "f"(c), "f"(d) : "memory");
}
__device__ __forceinline__ void red1(float* p, float a) {
    asm volatile("red.global.add.f32 [%0], %1;" :: "l"(p), "f"(a) : "memory");
}

// ---------------- kernel: zero V and S accumulators ----------------
// grid 520 x 256: 133120 float4 = 131072 (V) + 2048 (S)
__global__ void k_zero() {
    int i = blockIdx.x * blockDim.x + threadIdx.x;
    float4 z = make_float4(0.f, 0.f, 0.f, 0.f);
    if (i < (N_ * OUTD) / 4) {
        reinterpret_cast<float4*>(g_V)[i] = z;
    } else {
        reinterpret_cast<float4*>(g_S)[i - (N_ * OUTD) / 4] = z;
    }
}

// ---------------- kernel: h = input @ W ----------------
// grid 128 blocks x 256 threads, 64 rows/block, dynamic smem 132096 B
__global__ void __launch_bounds__(256) k_h(const float* __restrict__ input,
                                           const float* __restrict__ W) {
    extern __shared__ float sm[];
    float* in_s = sm;               // [64][260]  (260 = 16B-aligned, conflict-free rows)
    float* W_s  = sm + 64 * 260;    // [256][64]

    int t = threadIdx.x;
    int rowBase = blockIdx.x * 64;

    // stage W (16384 floats, linear)
#pragma unroll
    for (int m = 0; m < 16; m++) {
        int idx4 = t + 256 * m;
        *reinterpret_cast<float4*>(&W_s[4 * idx4]) =
            *reinterpret_cast<const float4*>(&W[4 * idx4]);
    }
    // stage input tile (64 x 256 floats)
#pragma unroll
    for (int m = 0; m < 16; m++) {
        int idx4 = t + 256 * m;
        int r  = idx4 >> 6;
        int k4 = (idx4 & 63) * 4;
        *reinterpret_cast<float4*>(&in_s[r * 260 + k4]) =
            *reinterpret_cast<const float4*>(&input[(size_t)(rowBase + r) * IND + k4]);
    }
    __syncthreads();

    int ty = t >> 3;   // 0..31 -> rows 2ty, 2ty+1
    int tx = t & 7;    // cols {4tx..4tx+3} and {32+4tx..35+4tx}

    ull acc[2][4];
#pragma unroll
    for (int r = 0; r < 2; r++)
#pragma unroll
        for (int g = 0; g < 4; g++) acc[r][g] = 0ull;

#pragma unroll 8
    for (int k = 0; k < IND; k++) {
        ulonglong2 wa = *reinterpret_cast<const ulonglong2*>(&W_s[k * 64 + 4 * tx]);
        ulonglong2 wb = *reinterpret_cast<const ulonglong2*>(&W_s[k * 64 + 32 + 4 * tx]);
#pragma unroll
        for (int r = 0; r < 2; r++) {
            ull iv = pk2(in_s[(2 * ty + r) * 260 + k]);
            ffma2(acc[r][0], iv, wa.x);
            ffma2(acc[r][1], iv, wa.y);
            ffma2(acc[r][2], iv, wb.x);
            ffma2(acc[r][3], iv, wb.y);
        }
    }

#pragma unroll
    for (int r = 0; r < 2; r++) {
        int row = rowBase + 2 * ty + r;
        float2 p0 = upk(acc[r][0]), p1 = upk(acc[r][1]);
        float2 p2 = upk(acc[r][2]), p3 = upk(acc[r][3]);
        *reinterpret_cast<float4*>(&g_h[row * OUTD + 4 * tx]) =
            make_float4(p0.x, p0.y, p1.x, p1.y);
        *reinterpret_cast<float4*>(&g_h[row * OUTD + 32 + 4 * tx]) =
            make_float4(p2.x, p2.y, p3.x, p3.y);
    }
}

// ---------------- kernel: f1 = h@a1, f2 = h@a2 (warp per row) ----------------
// grid 1024 x 256 (8 warps/block)
__global__ void __launch_bounds__(256) k_f(const float* __restrict__ a) {
    int warp = threadIdx.x >> 5, lane = threadIdx.x & 31;
    int row = blockIdx.x * 8 + warp;
    const float* hrow = g_h + (size_t)row * OUTD;
    float h0 = hrow[lane], h1 = hrow[lane + 32];
    float p1 = h0 * a[lane]      + h1 * a[lane + 32];
    float p2 = h0 * a[64 + lane] + h1 * a[96 + lane];
#pragma unroll
    for (int off = 16; off > 0; off >>= 1) {
        p1 += __shfl_xor_sync(0xFFFFFFFFu, p1, off);
        p2 += __shfl_xor_sync(0xFFFFFFFFu, p2, off);
    }
    if (lane == 0) {
        g_f1[row] = p1;
        g_f2[row] = p2;
    }
}

// ---------------- kernel: masked-softmax numerator/denominator ----------------
// grid (NS, 64) x 128 threads; dynamic smem 51200 B
__global__ void __launch_bounds__(128, 4) k_attn(const int* __restrict__ adj) {
    extern __shared__ float sm[];
    float* w_s  = sm;                       // [128][65]
    float* h_s  = sm + TM * WST;            // [64][68]
    float* f1_s = sm + TM * WST + TJ * HST; // [128]

    int t = threadIdx.x;
    int rowBase = blockIdx.y * TM;
    int jStart  = blockIdx.x * (N_ / NS);   // 256 j per split

    f1_s[t] = g_f1[rowBase + t];

    int ty = t >> 3;   // 0..15 -> rows ty*8..ty*8+7
    int tx = t & 7;    // cols {4tx..} and {32+4tx..}
    int tl = t & 15;   // j-quad for staging/gen
    int i0 = t >> 4;   // 0..7 row phase for gen

    ull acc[8][4];
#pragma unroll
    for (int r = 0; r < 8; r++)
#pragma unroll
        for (int g = 0; g < 4; g++) acc[r][g] = 0ull;
    float srow = 0.f;

    for (int chunk = 0; chunk < (N_ / NS) / TJ; chunk++) {  // 4 chunks
        int jb = jStart + chunk * TJ;
        __syncthreads();   // protect w_s/h_s from previous iteration's readers

        // stage h chunk [64 j][64 c]
#pragma unroll
        for (int m = 0; m < 8; m++) {
            int idx4 = t + 128 * m;
            int jj = idx4 >> 4;
            int c4 = (idx4 & 15) * 4;
            *reinterpret_cast<float4*>(&h_s[jj * HST + c4]) =
                *reinterpret_cast<const float4*>(&g_h[(size_t)(jb + jj) * OUTD + c4]);
        }

        // generate w tile [128 i][64 j]: w = adj>0 ? exp(lrelu(f1+f2)) : 0
        float4 f2v = *reinterpret_cast<const float4*>(&g_f2[jb + 4 * tl]);
#pragma unroll 4
        for (int m = 0; m < 16; m++) {
            int i = i0 + 8 * m;
            int4 av = __ldcs(reinterpret_cast<const int4*>(
                &adj[(size_t)(rowBase + i) * N_ + jb + 4 * tl]));
            float f1v = f1_s[i];
            float x0 = f1v + f2v.x; x0 = fmaxf(x0, 0.01f * x0);
            float x1 = f1v + f2v.y; x1 = fmaxf(x1, 0.01f * x1);
            float x2 = f1v + f2v.z; x2 = fmaxf(x2, 0.01f * x2);
            float x3 = f1v + f2v.w; x3 = fmaxf(x3, 0.01f * x3);
            float* wr = &w_s[i * WST + 4 * tl];
            wr[0] = (av.x > 0) ? __expf(x0) : 0.f;
            wr[1] = (av.y > 0) ? __expf(x1) : 0.f;
            wr[2] = (av.z > 0) ? __expf(x2) : 0.f;
            wr[3] = (av.w > 0) ? __expf(x3) : 0.f;
        }
        __syncthreads();

        // row sum (thread t owns row t), 4-way ILP
        {
            float s0 = 0.f, s1 = 0.f, s2 = 0.f, s3 = 0.f;
            const float* wr = &w_s[t * WST];
#pragma unroll
            for (int jj = 0; jj < TJ; jj += 4) {
                s0 += wr[jj + 0];
                s1 += wr[jj + 1];
                s2 += wr[jj + 2];
                s3 += wr[jj + 3];
            }
            srow += (s0 + s1) + (s2 + s3);
        }

        // GEMM: acc += w[rows][jj] * h[jj][cols]
#pragma unroll 4
        for (int jj = 0; jj < TJ; jj++) {
            ulonglong2 ha = *reinterpret_cast<const ulonglong2*>(&h_s[jj * HST + 4 * tx]);
            ulonglong2 hb = *reinterpret_cast<const ulonglong2*>(&h_s[jj * HST + 32 + 4 * tx]);
#pragma unroll
            for (int r = 0; r < 8; r++) {
                ull w2 = pk2(w_s[(ty * 8 + r) * WST + jj]);
                ffma2(acc[r][0], w2, ha.x);
                ffma2(acc[r][1], w2, ha.y);
                ffma2(acc[r][2], w2, hb.x);
                ffma2(acc[r][3], w2, hb.y);
            }
        }
    }

    // epilogue: global reduction
    red1(&g_S[rowBase + t], srow);
#pragma unroll
    for (int r = 0; r < 8; r++) {
        int row = rowBase + ty * 8 + r;
        float2 p0 = upk(acc[r][0]), p1 = upk(acc[r][1]);
        float2 p2 = upk(acc[r][2]), p3 = upk(acc[r][3]);
        red4(&g_V[row * OUTD + 4 * tx],      p0.x, p0.y, p1.x, p1.y);
        red4(&g_V[row * OUTD + 32 + 4 * tx], p2.x, p2.y, p3.x, p3.y);
    }
}

// ---------------- kernel: normalize + scalar outputs ----------------
// grid 2048 x 256
__global__ void k_fin(float* __restrict__ out) {
    int gid = blockIdx.x * blockDim.x + threadIdx.x;
    out[gid] = g_V[gid] / g_S[gid >> 6];
    if (gid < 3) {
        float x;
        if (gid == 0)      x = g_f1[1] + g_f2[2];   // face_Rhand = e[1,2]
        else if (gid == 1) x = g_f1[1] + g_f2[3];   // face_Lhand = e[1,3]
        else               x = g_f1[3] + g_f2[2];   // Rhand_Lhand = e[3,2]
        out[N_ * OUTD + gid] = fmaxf(x, 0.01f * x);
    }
}

// ---------------- launch ----------------
extern "C" void kernel_launch(void* const* d_in, const int* in_sizes, int n_in,
                              void* d_out, int out_size) {
    const float* input = (const float*)d_in[0];
    const int*   adj   = (const int*)  d_in[1];
    const float* W     = (const float*)d_in[2];
    const float* a     = (const float*)d_in[3];
    float*       out   = (float*)d_out;

    (void)in_sizes; (void)n_in; (void)out_size;

    const int smem_h    = (64 * 260 + 256 * 64) * 4;            // 132096 B
    const int smem_attn = (TM * WST + TJ * HST + TM) * 4;       // 51200 B
    cudaFuncSetAttribute(k_h,    cudaFuncAttributeMaxDynamicSharedMemorySize, smem_h);
    cudaFuncSetAttribute(k_attn, cudaFuncAttributeMaxDynamicSharedMemorySize, smem_attn);

    k_zero<<<520, 256>>>();
    k_h   <<<128, 256, smem_h>>>(input, W);
    k_f   <<<1024, 256>>>(a);
    k_attn<<<dim3(NS, N_ / TM), 128, smem_attn>>>(adj);
    k_fin <<<2048, 256>>>(out);
}

// round 3
// speedup vs baseline: 1.3098x; 1.3098x over previous
#include <cuda_runtime.h>
#include <cstdint>
#include <cstddef>

#define N_    8192
#define IND   256
#define OUTD  64
#define NS    64        // j splits -> 4096 attention blocks
#define TM    128       // rows per attention block
#define TJ    64        // j chunk
#define WST   68        // w_s row stride (floats, 16B-aligned rows)
#define HST   68        // h_s row stride (floats, 16B-aligned rows)

// ---------------- device scratch (no runtime allocation allowed) ----------------
__device__ __align__(16) float g_h [N_ * OUTD];
__device__ __align__(16) float g_f1[N_];
__device__ __align__(16) float g_f2[N_];
__device__ __align__(16) float g_V [N_ * OUTD];
__device__ __align__(16) float g_S [N_];

typedef unsigned long long ull;

// ---------------- packed f32x2 helpers (sm_100+) ----------------
__device__ __forceinline__ ull pk2(float x) {
    ull u;
    asm("mov.b64 %0, {%1, %1};" : "=l"(u) : "r"(__float_as_uint(x)));
    return u;
}
__device__ __forceinline__ void ffma2(ull& d, ull a, ull b) {
    asm("fma.rn.f32x2 %0, %1, %2, %0;" : "+l"(d) : "l"(a), "l"(b));
}
__device__ __forceinline__ float2 upk(ull u) {
    float2 f;
    asm("mov.b64 {%0, %1}, %2;" : "=f"(f.x), "=f"(f.y) : "l"(u));
    return f;
}
__device__ __forceinline__ void red4(float* p, float a, float b, float c, float d) {
    asm volatile("red.global.add.v4.f32 [%0], {%1, %2, %3, %4};"
                 :: "l"(p), "f"(a), "f"(b), "f"(c), "f"(d) : "memory");
}
__device__ __forceinline__ void red1(float* p, float a) {
    asm volatile("red.global.add.f32 [%0], %1;" :: "l"(p), "f"(a) : "memory");
}

// ---------------- kernel: zero V and S accumulators ----------------
__global__ void k_zero() {
    int i = blockIdx.x * blockDim.x + threadIdx.x;
    float4 z = make_float4(0.f, 0.f, 0.f, 0.f);
    if (i < (N_ * OUTD) / 4) {
        reinterpret_cast<float4*>(g_V)[i] = z;
    } else {
        reinterpret_cast<float4*>(g_S)[i - (N_ * OUTD) / 4] = z;
    }
}

// ---------------- kernel: h = input @ W ----------------
__global__ void __launch_bounds__(256) k_h(const float* __restrict__ input,
                                           const float* __restrict__ W) {
    extern __shared__ float sm[];
    float* in_s = sm;               // [64][260]
    float* W_s  = sm + 64 * 260;    // [256][64]

    int t = threadIdx.x;
    int rowBase = blockIdx.x * 64;

#pragma unroll
    for (int m = 0; m < 16; m++) {
        int idx4 = t + 256 * m;
        *reinterpret_cast<float4*>(&W_s[4 * idx4]) =
            *reinterpret_cast<const float4*>(&W[4 * idx4]);
    }
#pragma unroll
    for (int m = 0; m < 16; m++) {
        int idx4 = t + 256 * m;
        int r  = idx4 >> 6;
        int k4 = (idx4 & 63) * 4;
        *reinterpret_cast<float4*>(&in_s[r * 260 + k4]) =
            *reinterpret_cast<const float4*>(&input[(size_t)(rowBase + r) * IND + k4]);
    }
    __syncthreads();

    int ty = t >> 3;
    int tx = t & 7;

    ull acc[2][4];
#pragma unroll
    for (int r = 0; r < 2; r++)
#pragma unroll
        for (int g = 0; g < 4; g++) acc[r][g] = 0ull;

#pragma unroll 8
    for (int k = 0; k < IND; k++) {
        ulonglong2 wa = *reinterpret_cast<const ulonglong2*>(&W_s[k * 64 + 4 * tx]);
        ulonglong2 wb = *reinterpret_cast<const ulonglong2*>(&W_s[k * 64 + 32 + 4 * tx]);
#pragma unroll
        for (int r = 0; r < 2; r++) {
            ull iv = pk2(in_s[(2 * ty + r) * 260 + k]);
            ffma2(acc[r][0], iv, wa.x);
            ffma2(acc[r][1], iv, wa.y);
            ffma2(acc[r][2], iv, wb.x);
            ffma2(acc[r][3], iv, wb.y);
        }
    }

#pragma unroll
    for (int r = 0; r < 2; r++) {
        int row = rowBase + 2 * ty + r;
        float2 p0 = upk(acc[r][0]), p1 = upk(acc[r][1]);
        float2 p2 = upk(acc[r][2]), p3 = upk(acc[r][3]);
        *reinterpret_cast<float4*>(&g_h[row * OUTD + 4 * tx]) =
            make_float4(p0.x, p0.y, p1.x, p1.y);
        *reinterpret_cast<float4*>(&g_h[row * OUTD + 32 + 4 * tx]) =
            make_float4(p2.x, p2.y, p3.x, p3.y);
    }
}

// ---------------- kernel: f1 = h@a1, f2 = h@a2 (warp per row) ----------------
__global__ void __launch_bounds__(256) k_f(const float* __restrict__ a) {
    int warp = threadIdx.x >> 5, lane = threadIdx.x & 31;
    int row = blockIdx.x * 8 + warp;
    const float* hrow = g_h + (size_t)row * OUTD;
    float h0 = hrow[lane], h1 = hrow[lane + 32];
    float p1 = h0 * a[lane]      + h1 * a[lane + 32];
    float p2 = h0 * a[64 + lane] + h1 * a[96 + lane];
#pragma unroll
    for (int off = 16; off > 0; off >>= 1) {
        p1 += __shfl_xor_sync(0xFFFFFFFFu, p1, off);
        p2 += __shfl_xor_sync(0xFFFFFFFFu, p2, off);
    }
    if (lane == 0) {
        g_f1[row] = p1;
        g_f2[row] = p2;
    }
}

// ---------------- kernel: masked-softmax numerator/denominator ----------------
// grid (NS, 64) x 256 threads; dynamic smem 52736 B; 4 blocks/SM (32 warps)
__global__ void __launch_bounds__(256, 4) k_attn(const int* __restrict__ adj) {
    extern __shared__ float sm[];
    float* w_s  = sm;                        // [128][68]
    float* h_s  = sm + TM * WST;             // [64][68]
    float* f1_s = sm + TM * WST + TJ * HST;  // [128]

    int t = threadIdx.x;
    int rowBase = blockIdx.y * TM;
    int jStart  = blockIdx.x * (N_ / NS);    // 128 j per split

    if (t < TM) f1_s[t] = g_f1[rowBase + t];

    const int ty = t >> 3;    // 0..31: rows ty + 32k
    const int tx = t & 7;     // cols {4tx..} and {32+4tx..}
    const int tl = t & 15;    // j-quad for staging/gen
    const int i0 = t >> 4;    // 0..15 row phase for gen

    ull acc[4][4];
#pragma unroll
    for (int k = 0; k < 4; k++)
#pragma unroll
        for (int g = 0; g < 4; g++) acc[k][g] = 0ull;
    float srow = 0.f;

    for (int c = 0; c < (N_ / NS) / TJ; c++) {   // 2 chunks
        int jb = jStart + c * TJ;
        __syncthreads();   // previous chunk's readers done

        // stage h chunk [64 j][64 c] (4 float4 per thread)
#pragma unroll
        for (int m = 0; m < 4; m++) {
            int idx = t + 256 * m;
            int jj = idx >> 4;
            int c4 = (idx & 15) << 2;
            *reinterpret_cast<float4*>(&h_s[jj * HST + c4]) =
                *reinterpret_cast<const float4*>(&g_h[(size_t)(jb + jj) * OUTD + c4]);
        }

        // generate w tile [128 i][64 j]: w = adj>0 ? exp(lrelu(f1+f2)) : 0
        float4 f2v = *reinterpret_cast<const float4*>(&g_f2[jb + 4 * tl]);
#pragma unroll
        for (int half = 0; half < 2; half++) {
            int4 av[4];
#pragma unroll
            for (int m = 0; m < 4; m++) {
                int i = i0 + 16 * (4 * half + m);
                av[m] = __ldcs(reinterpret_cast<const int4*>(
                    &adj[(size_t)(rowBase + i) * N_ + jb + 4 * tl]));
            }
#pragma unroll
            for (int m = 0; m < 4; m++) {
                int i = i0 + 16 * (4 * half + m);
                float f1v = f1_s[i];
                float x0 = f1v + f2v.x; x0 = fmaxf(x0, 0.01f * x0);
                float x1 = f1v + f2v.y; x1 = fmaxf(x1, 0.01f * x1);
                float x2 = f1v + f2v.z; x2 = fmaxf(x2, 0.01f * x2);
                float x3 = f1v + f2v.w; x3 = fmaxf(x3, 0.01f * x3);
                float4 wv;
                wv.x = (av[m].x > 0) ? __expf(x0) : 0.f;
                wv.y = (av[m].y > 0) ? __expf(x1) : 0.f;
                wv.z = (av[m].z > 0) ? __expf(x2) : 0.f;
                wv.w = (av[m].w > 0) ? __expf(x3) : 0.f;
                *reinterpret_cast<float4*>(&w_s[i * WST + 4 * tl]) = wv;
            }
        }
        __syncthreads();

        // row sum: thread pair (t, t^1) shares row t>>1, 32 cols each
        {
            const float* wr = &w_s[(t >> 1) * WST + ((t & 1) << 5)];
            float s0 = 0.f, s1 = 0.f, s2 = 0.f, s3 = 0.f;
#pragma unroll
            for (int j4 = 0; j4 < 32; j4 += 4) {
                s0 += wr[j4 + 0];
                s1 += wr[j4 + 1];
                s2 += wr[j4 + 2];
                s3 += wr[j4 + 3];
            }
            float part = (s0 + s1) + (s2 + s3);
            part += __shfl_xor_sync(0xFFFFFFFFu, part, 1);
            if (!(t & 1)) srow += part;
        }

        // GEMM: acc[k][g] += w[ty+32k][jj] * h[jj][cols]
#pragma unroll 8
        for (int jg = 0; jg < TJ; jg += 2) {
            ulonglong2 ha0 = *reinterpret_cast<const ulonglong2*>(&h_s[jg * HST + 4 * tx]);
            ulonglong2 hb0 = *reinterpret_cast<const ulonglong2*>(&h_s[jg * HST + 32 + 4 * tx]);
            ulonglong2 ha1 = *reinterpret_cast<const ulonglong2*>(&h_s[(jg + 1) * HST + 4 * tx]);
            ulonglong2 hb1 = *reinterpret_cast<const ulonglong2*>(&h_s[(jg + 1) * HST + 32 + 4 * tx]);
#pragma unroll
            for (int k = 0; k < 4; k++) {
                float2 wp = *reinterpret_cast<const float2*>(&w_s[(ty + 32 * k) * WST + jg]);
                ull w0 = pk2(wp.x);
                ull w1 = pk2(wp.y);
                ffma2(acc[k][0], w0, ha0.x);
                ffma2(acc[k][1], w0, ha0.y);
                ffma2(acc[k][2], w0, hb0.x);
                ffma2(acc[k][3], w0, hb0.y);
                ffma2(acc[k][0], w1, ha1.x);
                ffma2(acc[k][1], w1, ha1.y);
                ffma2(acc[k][2], w1, hb1.x);
                ffma2(acc[k][3], w1, hb1.y);
            }
        }
    }

    // epilogue: global reduction
    if (!(t & 1)) red1(&g_S[rowBase + (t >> 1)], srow);
#pragma unroll
    for (int k = 0; k < 4; k++) {
        int row = rowBase + ty + 32 * k;
        float2 p0 = upk(acc[k][0]), p1 = upk(acc[k][1]);
        float2 p2 = upk(acc[k][2]), p3 = upk(acc[k][3]);
        red4(&g_V[row * OUTD + 4 * tx],      p0.x, p0.y, p1.x, p1.y);
        red4(&g_V[row * OUTD + 32 + 4 * tx], p2.x, p2.y, p3.x, p3.y);
    }
}

// ---------------- kernel: normalize + scalar outputs ----------------
__global__ void k_fin(float* __restrict__ out) {
    int gid = blockIdx.x * blockDim.x + threadIdx.x;
    out[gid] = g_V[gid] / g_S[gid >> 6];
    if (gid < 3) {
        float x;
        if (gid == 0)      x = g_f1[1] + g_f2[2];   // face_Rhand = e[1,2]
        else if (gid == 1) x = g_f1[1] + g_f2[3];   // face_Lhand = e[1,3]
        else               x = g_f1[3] + g_f2[2];   // Rhand_Lhand = e[3,2]
        out[N_ * OUTD + gid] = fmaxf(x, 0.01f * x);
    }
}

// ---------------- launch ----------------
extern "C" void kernel_launch(void* const* d_in, const int* in_sizes, int n_in,
                              void* d_out, int out_size) {
    const float* input = (const float*)d_in[0];
    const int*   adj   = (const int*)  d_in[1];
    const float* W     = (const float*)d_in[2];
    const float* a     = (const float*)d_in[3];
    float*       out   = (float*)d_out;

    (void)in_sizes; (void)n_in; (void)out_size;

    const int smem_h    = (64 * 260 + 256 * 64) * 4;            // 132096 B
    const int smem_attn = (TM * WST + TJ * HST + TM) * 4;       // 52736 B
    cudaFuncSetAttribute(k_h,    cudaFuncAttributeMaxDynamicSharedMemorySize, smem_h);
    cudaFuncSetAttribute(k_attn, cudaFuncAttributeMaxDynamicSharedMemorySize, smem_attn);

    k_zero<<<520, 256>>>();
    k_h   <<<128, 256, smem_h>>>(input, W);
    k_f   <<<1024, 256>>>(a);
    k_attn<<<dim3(NS, N_ / TM), 256, smem_attn>>>(adj);
    k_fin <<<2048, 256>>>(out);
}

// round 5
// speedup vs baseline: 1.8686x; 1.4266x over previous
#include <cuda_runtime.h>
#include <cstdint>
#include <cstddef>

#define N_    8192
#define IND   256
#define OUTD  64
#define NS    32                 // j splits -> 2048 attention blocks
#define TM    128                // rows per attention block
#define TJ    32                 // jj per chunk
#define CH    ((N_ / NS) / TJ)   // 8 chunks per block
#define WSTR  36                 // w_s row stride (floats)
#define HSTR  36                 // hT_s row stride (floats)

// ---------------- device scratch (no runtime allocation allowed) ----------------
__device__ __align__(16) float g_h [N_ * OUTD];
__device__ __align__(16) float g_hT[OUTD * N_];   // transposed, tf32-rounded
__device__ __align__(16) float g_f1[N_];
__device__ __align__(16) float g_f2[N_];
__device__ __align__(16) float g_V [N_ * OUTD];
__device__ __align__(16) float g_S [N_];

typedef unsigned long long ull;

// ---------------- helpers ----------------
__device__ __forceinline__ ull pk2(float x) {
    ull u; asm("mov.b64 %0, {%1, %1};" : "=l"(u) : "r"(__float_as_uint(x))); return u;
}
__device__ __forceinline__ void ffma2(ull& d, ull a, ull b) {
    asm("fma.rn.f32x2 %0, %1, %2, %0;" : "+l"(d) : "l"(a), "l"(b));
}
__device__ __forceinline__ float2 upk(ull u) {
    float2 f; asm("mov.b64 {%0, %1}, %2;" : "=f"(f.x), "=f"(f.y) : "l"(u)); return f;
}
__device__ __forceinline__ void red4(float* p, float a, float b, float c, float d) {
    asm volatile("red.global.add.v4.f32 [%0], {%1, %2, %3, %4};"
                 :: "l"(p), "f"(a), "f"(b), "f"(c), "f"(d) : "memory");
}
__device__ __forceinline__ void red2(float* p, float a, float b) {
    asm volatile("red.global.add.v2.f32 [%0], {%1, %2};"
                 :: "l"(p), "f"(a), "f"(b) : "memory");
}
__device__ __forceinline__ void red1(float* p, float a) {
    asm volatile("red.global.add.f32 [%0], %1;" :: "l"(p), "f"(a) : "memory");
}
__device__ __forceinline__ uint32_t tf32r(float f) {
    uint32_t u; asm("cvt.rna.tf32.f32 %0, %1;" : "=r"(u) : "f"(f)); return u;
}

// tf32 tensor-core mma: D(16x8) += A(16x8) * B(8x8), row.col
__device__ __forceinline__ void mma8(float* d, const uint32_t* a, const uint32_t* b) {
    asm volatile("mma.sync.aligned.m16n8k8.row.col.f32.tf32.tf32.f32 "
                 "{%0,%1,%2,%3}, {%4,%5,%6,%7}, {%8,%9}, {%0,%1,%2,%3};"
                 : "+f"(d[0]), "+f"(d[1]), "+f"(d[2]), "+f"(d[3])
                 : "r"(a[0]), "r"(a[1]), "r"(a[2]), "r"(a[3]),
                   "r"(b[0]), "r"(b[1]));
}

// ---------------- kernel: zero V and S accumulators ----------------
__global__ void k_zero() {
    int i = blockIdx.x * blockDim.x + threadIdx.x;
    float4 z = make_float4(0.f, 0.f, 0.f, 0.f);
    if (i < (N_ * OUTD) / 4) reinterpret_cast<float4*>(g_V)[i] = z;
    else                     reinterpret_cast<float4*>(g_S)[i - (N_ * OUTD) / 4] = z;
}

// ---------------- kernel: h = input @ W (f32x2 FFMA) ----------------
__global__ void __launch_bounds__(256) k_h(const float* __restrict__ input,
                                           const float* __restrict__ W) {
    extern __shared__ float sm[];
    float* in_s = sm;
    float* W_s  = sm + 64 * 260;
    int t = threadIdx.x;
    int rowBase = blockIdx.x * 64;

#pragma unroll
    for (int m = 0; m < 16; m++) {
        int idx4 = t + 256 * m;
        *reinterpret_cast<float4*>(&W_s[4 * idx4]) =
            *reinterpret_cast<const float4*>(&W[4 * idx4]);
    }
#pragma unroll
    for (int m = 0; m < 16; m++) {
        int idx4 = t + 256 * m;
        int r = idx4 >> 6, k4 = (idx4 & 63) * 4;
        *reinterpret_cast<float4*>(&in_s[r * 260 + k4]) =
            *reinterpret_cast<const float4*>(&input[(size_t)(rowBase + r) * IND + k4]);
    }
    __syncthreads();

    int ty = t >> 3, tx = t & 7;
    ull acc[2][4];
#pragma unroll
    for (int r = 0; r < 2; r++)
#pragma unroll
        for (int g = 0; g < 4; g++) acc[r][g] = 0ull;

#pragma unroll 8
    for (int k = 0; k < IND; k++) {
        ulonglong2 wa = *reinterpret_cast<const ulonglong2*>(&W_s[k * 64 + 4 * tx]);
        ulonglong2 wb = *reinterpret_cast<const ulonglong2*>(&W_s[k * 64 + 32 + 4 * tx]);
#pragma unroll
        for (int r = 0; r < 2; r++) {
            ull iv = pk2(in_s[(2 * ty + r) * 260 + k]);
            ffma2(acc[r][0], iv, wa.x); ffma2(acc[r][1], iv, wa.y);
            ffma2(acc[r][2], iv, wb.x); ffma2(acc[r][3], iv, wb.y);
        }
    }
#pragma unroll
    for (int r = 0; r < 2; r++) {
        int row = rowBase + 2 * ty + r;
        float2 p0 = upk(acc[r][0]), p1 = upk(acc[r][1]);
        float2 p2 = upk(acc[r][2]), p3 = upk(acc[r][3]);
        *reinterpret_cast<float4*>(&g_h[row * OUTD + 4 * tx]) = make_float4(p0.x, p0.y, p1.x, p1.y);
        *reinterpret_cast<float4*>(&g_h[row * OUTD + 32 + 4 * tx]) = make_float4(p2.x, p2.y, p3.x, p3.y);
    }
}

// ---------------- kernel: f1 = h@a1, f2 = h@a2 ----------------
__global__ void __launch_bounds__(256) k_f(const float* __restrict__ a) {
    int warp = threadIdx.x >> 5, lane = threadIdx.x & 31;
    int row = blockIdx.x * 8 + warp;
    const float* hrow = g_h + (size_t)row * OUTD;
    float h0 = hrow[lane], h1 = hrow[lane + 32];
    float p1 = h0 * a[lane]      + h1 * a[lane + 32];
    float p2 = h0 * a[64 + lane] + h1 * a[96 + lane];
#pragma unroll
    for (int off = 16; off > 0; off >>= 1) {
        p1 += __shfl_xor_sync(0xFFFFFFFFu, p1, off);
        p2 += __shfl_xor_sync(0xFFFFFFFFu, p2, off);
    }
    if (lane == 0) { g_f1[row] = p1; g_f2[row] = p2; }
}

// ---------------- kernel: hT[c][j] = tf32(h[j][c]) ----------------
__global__ void __launch_bounds__(256) k_hT() {
    __shared__ float tile[64][65];
    int t = threadIdx.x;
    int jBase = blockIdx.x * 64;
#pragma unroll
    for (int m = 0; m < 4; m++) {
        int idx = t + 256 * m;
        int j = idx >> 4, c4 = (idx & 15) * 4;
        float4 v = *reinterpret_cast<const float4*>(&g_h[(size_t)(jBase + j) * OUTD + c4]);
        tile[j][c4] = v.x; tile[j][c4 + 1] = v.y; tile[j][c4 + 2] = v.z; tile[j][c4 + 3] = v.w;
    }
    __syncthreads();
#pragma unroll
    for (int m = 0; m < 4; m++) {
        int idx = t + 256 * m;
        int cc = idx >> 4, j4 = (idx & 15) * 4;
        uint4 o;
        o.x = tf32r(tile[j4 + 0][cc]); o.y = tf32r(tile[j4 + 1][cc]);
        o.z = tf32r(tile[j4 + 2][cc]); o.w = tf32r(tile[j4 + 3][cc]);
        *reinterpret_cast<uint4*>(&g_hT[(size_t)cc * N_ + jBase + j4]) = o;
    }
}

// ---------------- kernel: tf32 mma.sync weighted-GEMM attention ----------------
// grid (NS, 64) x 256 threads; static smem ~28KB
__global__ void __launch_bounds__(256, 2) k_attn(const int* __restrict__ adj) {
    __shared__ float w_s [TM * WSTR];   // 128 x 32 tf32 w tile (stride 36)
    __shared__ float hT_s[64 * HSTR];   // 64 c x 32 j tf32 h tile (stride 36)
    __shared__ float f1_s[TM];

    int t = threadIdx.x;
    int wid = t >> 5, lane = t & 31;
    int rowBase = blockIdx.y * TM;
    int jStart  = blockIdx.x * (N_ / NS);   // 256 j per split

    if (t < TM) f1_s[t] = g_f1[rowBase + t];

    const int jl = t & 7;     // j quad 4*jl (gen/stage)
    const int i0 = t >> 3;    // rows i0 + 32m (gen)

    // warp tiling: 4 m-groups x 2 n-groups; 2 m-tiles x 4 n-tiles per warp
    const int wm = wid >> 1;          // m-tiles 2wm, 2wm+1 (16 rows each)
    const int wn = wid & 1;           // n-tiles 4wn..4wn+3 (8 cols each)
    const int fr = lane >> 2;         // fragment row group 0..7
    const int fc = lane & 3;          // fragment col group 0..3

    float acc[2][4][4];
#pragma unroll
    for (int p = 0; p < 2; p++)
#pragma unroll
        for (int q = 0; q < 4; q++)
#pragma unroll
            for (int g = 0; g < 4; g++) acc[p][q][g] = 0.f;
    float srow[4] = {0.f, 0.f, 0.f, 0.f};

    // preload chunk-0 adj (4 rows x int4 per thread)
    int4 av[4];
    {
        const int* ar = adj + (size_t)(rowBase + i0) * N_ + jStart + 4 * jl;
#pragma unroll
        for (int m = 0; m < 4; m++) av[m] = __ldcs((const int4*)(ar + (size_t)32 * m * N_));
    }
    __syncthreads();   // f1_s visible

    for (int ch = 0; ch < CH; ch++) {
        int jb = jStart + ch * TJ;

        // stage hT chunk: hT_s[c][k] = g_hT[c][jb+k], 64 x 32
#pragma unroll
        for (int m = 0; m < 2; m++) {
            int idx = t + 256 * m;          // 0..511
            int cc = idx >> 3, q = idx & 7;
            *reinterpret_cast<float4*>(&hT_s[cc * HSTR + 4 * q]) =
                *reinterpret_cast<const float4*>(&g_hT[(size_t)cc * N_ + jb + 4 * q]);
        }

        // generate w tile (tf32-rounded) + register row-sums
        float4 f2v = *reinterpret_cast<const float4*>(&g_f2[jb + 4 * jl]);
#pragma unroll
        for (int m = 0; m < 4; m++) {
            int i = i0 + 32 * m;
            float f1v = f1_s[i];
            float x0 = f1v + f2v.x; x0 = fmaxf(x0, 0.01f * x0);
            float x1 = f1v + f2v.y; x1 = fmaxf(x1, 0.01f * x1);
            float x2 = f1v + f2v.z; x2 = fmaxf(x2, 0.01f * x2);
            float x3 = f1v + f2v.w; x3 = fmaxf(x3, 0.01f * x3);
            uint4 wq;
            wq.x = (av[m].x > 0) ? tf32r(__expf(x0)) : 0u;
            wq.y = (av[m].y > 0) ? tf32r(__expf(x1)) : 0u;
            wq.z = (av[m].z > 0) ? tf32r(__expf(x2)) : 0u;
            wq.w = (av[m].w > 0) ? tf32r(__expf(x3)) : 0u;
            *reinterpret_cast<uint4*>(&w_s[i * WSTR + 4 * jl]) = wq;
            float s = (__uint_as_float(wq.x) + __uint_as_float(wq.y))
                    + (__uint_as_float(wq.z) + __uint_as_float(wq.w));
            s += __shfl_xor_sync(0xFFFFFFFFu, s, 1);
            s += __shfl_xor_sync(0xFFFFFFFFu, s, 2);
            s += __shfl_xor_sync(0xFFFFFFFFu, s, 4);
            srow[m] += s;                    // valid on jl==0 lanes
        }

        // prefetch next chunk's adj
        if (ch + 1 < CH) {
            const int* ar = adj + (size_t)(rowBase + i0) * N_ + jb + TJ + 4 * jl;
#pragma unroll
            for (int m = 0; m < 4; m++) av[m] = __ldcs((const int4*)(ar + (size_t)32 * m * N_));
        }
        __syncthreads();   // tiles ready

        // tensor-core GEMM over this chunk: 4 k-steps of 8
#pragma unroll
        for (int kk = 0; kk < 4; kk++) {
            int kb = kk * 8;
            uint32_t a[2][4], b[4][2];
#pragma unroll
            for (int p = 0; p < 2; p++) {
                const float* wr = &w_s[((2 * wm + p) * 16 + fr) * WSTR + kb + fc];
                a[p][0] = __float_as_uint(wr[0]);
                a[p][1] = __float_as_uint(wr[8 * WSTR]);
                a[p][2] = __float_as_uint(wr[4]);
                a[p][3] = __float_as_uint(wr[8 * WSTR + 4]);
            }
#pragma unroll
            for (int q = 0; q < 4; q++) {
                const float* hr = &hT_s[((4 * wn + q) * 8 + fr) * HSTR + kb + fc];
                b[q][0] = __float_as_uint(hr[0]);
                b[q][1] = __float_as_uint(hr[4]);
            }
#pragma unroll
            for (int p = 0; p < 2; p++)
#pragma unroll
                for (int q = 0; q < 4; q++)
                    mma8(acc[p][q], a[p], b[q]);
        }
        __syncthreads();   // mma reads done before next gen overwrites
    }

    // denominators
    if (jl == 0) {
#pragma unroll
        for (int m = 0; m < 4; m++) red1(&g_S[rowBase + i0 + 32 * m], srow[m]);
    }

    // numerators: D fragment -> red.global.add.v2
#pragma unroll
    for (int p = 0; p < 2; p++) {
        int row0 = rowBase + (2 * wm + p) * 16 + fr;
#pragma unroll
        for (int q = 0; q < 4; q++) {
            int col = (4 * wn + q) * 8 + 2 * fc;
            red2(&g_V[row0 * OUTD + col],       acc[p][q][0], acc[p][q][1]);
            red2(&g_V[(row0 + 8) * OUTD + col], acc[p][q][2], acc[p][q][3]);
        }
    }
}

// ---------------- kernel: normalize + scalar outputs ----------------
__global__ void k_fin(float* __restrict__ out) {
    int gid = blockIdx.x * blockDim.x + threadIdx.x;
    out[gid] = g_V[gid] / g_S[gid >> 6];
    if (gid < 3) {
        float x;
        if (gid == 0)      x = g_f1[1] + g_f2[2];   // face_Rhand = e[1,2]
        else if (gid == 1) x = g_f1[1] + g_f2[3];   // face_Lhand = e[1,3]
        else               x = g_f1[3] + g_f2[2];   // Rhand_Lhand = e[3,2]
        out[N_ * OUTD + gid] = fmaxf(x, 0.01f * x);
    }
}

// ---------------- launch ----------------
extern "C" void kernel_launch(void* const* d_in, const int* in_sizes, int n_in,
                              void* d_out, int out_size) {
    const float* input = (const float*)d_in[0];
    const int*   adj   = (const int*)  d_in[1];
    const float* W     = (const float*)d_in[2];
    const float* a     = (const float*)d_in[3];
    float*       out   = (float*)d_out;
    (void)in_sizes; (void)n_in; (void)out_size;

    const int smem_h = (64 * 260 + 256 * 64) * 4;   // 132096 B
    cudaFuncSetAttribute(k_h, cudaFuncAttributeMaxDynamicSharedMemorySize, smem_h);

    k_zero<<<520, 256>>>();
    k_h   <<<128, 256, smem_h>>>(input, W);
    k_f   <<<1024, 256>>>(a);
    k_hT  <<<128, 256>>>();
    k_attn<<<dim3(NS, N_ / TM), 256>>>(adj);
    k_fin <<<2048, 256>>>(out);
}